// round 10
// baseline (speedup 1.0000x reference)
#include <cuda_runtime.h>
#include <cuda_bf16.h>
#include <math.h>

#define N_NODES 100000
#define D_IN    64
#define D_H     32
#define TOTAL_H (N_NODES * D_H)
#define E_MAX   1600000
#define BM      128
#define XS      (BM + 4)

// ---------------- scratch (device globals) ----------------------------------
__device__ __align__(16) float g_ycp [TOTAL_H];   // x_customer @ W1l_r1
__device__ __align__(16) float g_ypc [TOTAL_H];   // x_product  @ W1l_r2
__device__ __align__(16) float g_linc[TOTAL_H];   // x_customer @ W1r_r2 + b1_r2
__device__ __align__(16) float g_linp[TOTAL_H];   // x_product  @ W1r_r1 + b1_r1
__device__ __align__(16) float g_gc  [N_NODES];   // per-customer folded scalar
__device__ int   g_cnt_p[N_NODES];                // in-degree (c2p dst)
__device__ int   g_cnt_c[N_NODES];                // in-degree (p2c dst)
__device__ int   g_off_p[N_NODES + 1];
__device__ int   g_off_c[N_NODES + 1];
__device__ int   g_cur_p[N_NODES];
__device__ int   g_cur_c[N_NODES];
__device__ int   g_adj_p[E_MAX];                  // src(customer) ids grouped by product
__device__ int   g_adj_c[E_MAX];                  // src(product) ids grouped by customer
__device__ float g_w2l_eff[D_H];
__device__ float g_w2r_eff[D_H];
__device__ float g_bias_eff[1];

// ---------------- kernels ---------------------------------------------------

__global__ void k_zero_cnt() {
    int i = blockIdx.x * blockDim.x + threadIdx.x;
    if (i < N_NODES) { g_cnt_p[i] = 0; g_cnt_c[i] = 0; }
}

__global__ void k_eff(const float* __restrict__ W2l, const float* __restrict__ W2r,
                      const float* __restrict__ b2, const float* __restrict__ Wlin,
                      const float* __restrict__ blin) {
    int i = threadIdx.x;  // 0..31
    float wl = 0.f, wr = 0.f;
    #pragma unroll
    for (int j = 0; j < D_H; ++j) {
        float wj = Wlin[j];
        wl += W2l[i * D_H + j] * wj;
        wr += W2r[i * D_H + j] * wj;
    }
    g_w2l_eff[i] = wl;
    g_w2r_eff[i] = wr;
    float bv = b2[i] * Wlin[i];
    #pragma unroll
    for (int o = 16; o; o >>= 1) bv += __shfl_xor_sync(0xffffffffu, bv, o);
    if (i == 0) g_bias_eff[0] = bv + blin[0];
}

// Register-tiled GEMM (proven): C[128 nodes][64 outs] = x @ [Wl | Wr], K=64.
__global__ void k_prep(const float* __restrict__ x,
                       const float* __restrict__ Wl, const float* __restrict__ Wr,
                       const float* __restrict__ b,
                       float* __restrict__ y, float* __restrict__ lin, int n) {
    __shared__ float sW[D_IN * 64];
    __shared__ float sX[D_IN * XS];
    __shared__ float sb2[D_H];
    int tid = threadIdx.x;

    for (int i = tid; i < D_IN * 8; i += 256) {
        int k = i >> 3, q = i & 7;
        reinterpret_cast<float4*>(sW)[k * 16 + q]     = reinterpret_cast<const float4*>(Wl)[i];
        reinterpret_cast<float4*>(sW)[k * 16 + 8 + q] = reinterpret_cast<const float4*>(Wr)[i];
    }
    if (tid < D_H) sb2[tid] = b[tid];

    int base = blockIdx.x * BM;
    for (int i = tid; i < BM * 16; i += 256) {
        int node = i >> 4;
        int q    = i & 15;
        int gn = base + node;
        float4 v = (gn < n) ? reinterpret_cast<const float4*>(x + (size_t)gn * D_IN)[q]
                            : make_float4(0.f, 0.f, 0.f, 0.f);
        int k4 = q * 4;
        sX[(k4 + 0) * XS + node] = v.x;
        sX[(k4 + 1) * XS + node] = v.y;
        sX[(k4 + 2) * XS + node] = v.z;
        sX[(k4 + 3) * XS + node] = v.w;
    }
    __syncthreads();

    int tn = tid & 15;
    int tm = tid >> 4;
    int n0 = tn * 4, m0 = tm * 8;

    float acc[8][4];
    #pragma unroll
    for (int i = 0; i < 8; ++i)
        #pragma unroll
        for (int j = 0; j < 4; ++j) acc[i][j] = 0.f;

    #pragma unroll 4
    for (int k = 0; k < D_IN; ++k) {
        float4 w  = *reinterpret_cast<const float4*>(&sW[k * 64 + n0]);
        float4 xa = *reinterpret_cast<const float4*>(&sX[k * XS + m0]);
        float4 xb = *reinterpret_cast<const float4*>(&sX[k * XS + m0 + 4]);
        float xm[8] = {xa.x, xa.y, xa.z, xa.w, xb.x, xb.y, xb.z, xb.w};
        #pragma unroll
        for (int i = 0; i < 8; ++i) {
            acc[i][0] += xm[i] * w.x;
            acc[i][1] += xm[i] * w.y;
            acc[i][2] += xm[i] * w.z;
            acc[i][3] += xm[i] * w.w;
        }
    }

    bool isLin = (tn >= 8);
    int col = isLin ? (n0 - 32) : n0;
    float4 bw = isLin ? *reinterpret_cast<const float4*>(&sb2[col])
                      : make_float4(0.f, 0.f, 0.f, 0.f);
    float* dst = isLin ? lin : y;
    #pragma unroll
    for (int i = 0; i < 8; ++i) {
        int gn = base + m0 + i;
        if (gn < n) {
            float4 v = make_float4(acc[i][0] + bw.x, acc[i][1] + bw.y,
                                   acc[i][2] + bw.z, acc[i][3] + bw.w);
            *reinterpret_cast<float4*>(dst + (size_t)gn * D_H + col) = v;
        }
    }
}

// Count both relations' dst degrees in one pass.
__global__ void k_count(const int* __restrict__ e_c2p, const int* __restrict__ e_p2c, int E) {
    int e = blockIdx.x * blockDim.x + threadIdx.x;
    if (e >= E) return;
    atomicAdd(&g_cnt_p[__ldg(&e_c2p[E + e])], 1);
    atomicAdd(&g_cnt_c[__ldg(&e_p2c[E + e])], 1);
}

// Single-block exclusive scan (proven correct in R2): cnt[n] -> off[n+1], cur=off.
__global__ void k_scan(const int* __restrict__ cnt, int* __restrict__ off,
                       int* __restrict__ cur, int n) {
    __shared__ int ssum[1024];
    int t = threadIdx.x;
    int chunk = (n + 1023) >> 10;
    int lo = t * chunk, hi = min(lo + chunk, n);
    int s = 0;
    for (int i = lo; i < hi; ++i) s += cnt[i];
    ssum[t] = s;
    __syncthreads();
    for (int d = 1; d < 1024; d <<= 1) {
        int v = (t >= d) ? ssum[t - d] : 0;
        __syncthreads();
        if (t >= d) ssum[t] += v;
        __syncthreads();
    }
    int run = (t == 0) ? 0 : ssum[t - 1];
    for (int i = lo; i < hi; ++i) {
        off[i] = run; cur[i] = run;
        run += cnt[i];
    }
    if (t == 1023) off[n] = ssum[1023];
}

// Fill both adjacency lists in one pass.
__global__ void k_fill(const int* __restrict__ e_c2p, const int* __restrict__ e_p2c, int E) {
    int e = blockIdx.x * blockDim.x + threadIdx.x;
    if (e >= E) return;
    {
        int s = __ldg(&e_c2p[e]);
        int d = __ldg(&e_c2p[E + e]);
        g_adj_p[atomicAdd(&g_cur_p[d], 1)] = s;
    }
    {
        int s = __ldg(&e_p2c[e]);
        int d = __ldg(&e_p2c[E + e]);
        g_adj_c[atomicAdd(&g_cur_c[d], 1)] = s;
    }
}

// Customer gather: mean over p2c neighbors of y_pc + lin_c, relu, dot(weff) -> g_c.
// Warp per node. adj loads are warp-uniform (broadcast); y loads coalesced 128B.
__global__ void k_gather_c(const int* __restrict__ off, const int* __restrict__ adj,
                           const float* __restrict__ y, const float* __restrict__ lin,
                           const float* __restrict__ weff, float* __restrict__ g, int n) {
    int j = threadIdx.x & 31;
    int node = (blockIdx.x * blockDim.x + threadIdx.x) >> 5;
    if (node >= n) return;
    int base = __ldg(&off[node]), end = __ldg(&off[node + 1]);
    float a0 = 0.f, a1 = 0.f, a2 = 0.f, a3 = 0.f;
    int i = base;
    for (; i + 4 <= end; i += 4) {
        int n0 = __ldg(&adj[i]);
        int n1 = __ldg(&adj[i + 1]);
        int n2 = __ldg(&adj[i + 2]);
        int n3 = __ldg(&adj[i + 3]);
        a0 += __ldg(y + (size_t)n0 * D_H + j);
        a1 += __ldg(y + (size_t)n1 * D_H + j);
        a2 += __ldg(y + (size_t)n2 * D_H + j);
        a3 += __ldg(y + (size_t)n3 * D_H + j);
    }
    for (; i < end; ++i) {
        int nk = __ldg(&adj[i]);
        a0 += __ldg(y + (size_t)nk * D_H + j);
    }
    float mean = (a0 + a1 + a2 + a3) / fmaxf((float)(end - base), 1.0f);
    float h = fmaxf(mean + __ldg(lin + (size_t)node * D_H + j), 0.0f);
    float v = h * __ldg(weff + j);
    #pragma unroll
    for (int o = 16; o; o >>= 1) v += __shfl_xor_sync(0xffffffffu, v, o);
    if (j == 0) g[node] = v;
}

// Product gather: layer1 mean of y_cp AND layer2 mean of g_c over the same CSR,
// then h=relu(mean+lin_p), out = sigmoid(mean_gc + dot(h,weff) + bias).
__global__ void k_gather_p(const int* __restrict__ off, const int* __restrict__ adj,
                           const float* __restrict__ y, const float* __restrict__ lin,
                           const float* __restrict__ weff, const float* __restrict__ gc,
                           float* __restrict__ out, int n) {
    int j = threadIdx.x & 31;
    int node = (blockIdx.x * blockDim.x + threadIdx.x) >> 5;
    if (node >= n) return;
    int base = __ldg(&off[node]), end = __ldg(&off[node + 1]);
    float a0 = 0.f, a1 = 0.f, a2 = 0.f, a3 = 0.f;
    float s0 = 0.f, s1 = 0.f, s2 = 0.f, s3 = 0.f;
    int i = base;
    for (; i + 4 <= end; i += 4) {
        int n0 = __ldg(&adj[i]);
        int n1 = __ldg(&adj[i + 1]);
        int n2 = __ldg(&adj[i + 2]);
        int n3 = __ldg(&adj[i + 3]);
        a0 += __ldg(y + (size_t)n0 * D_H + j);  s0 += __ldg(gc + n0);
        a1 += __ldg(y + (size_t)n1 * D_H + j);  s1 += __ldg(gc + n1);
        a2 += __ldg(y + (size_t)n2 * D_H + j);  s2 += __ldg(gc + n2);
        a3 += __ldg(y + (size_t)n3 * D_H + j);  s3 += __ldg(gc + n3);
    }
    for (; i < end; ++i) {
        int nk = __ldg(&adj[i]);
        a0 += __ldg(y + (size_t)nk * D_H + j);
        s0 += __ldg(gc + nk);
    }
    float inv = 1.0f / fmaxf((float)(end - base), 1.0f);
    float mean    = (a0 + a1 + a2 + a3) * inv;
    float mean_gc = (s0 + s1 + s2 + s3) * inv;
    float h = fmaxf(mean + __ldg(lin + (size_t)node * D_H + j), 0.0f);
    float v = h * __ldg(weff + j);
    #pragma unroll
    for (int o = 16; o; o >>= 1) v += __shfl_xor_sync(0xffffffffu, v, o);
    if (j == 0) {
        float logit = mean_gc + v + g_bias_eff[0];
        out[node] = 1.0f / (1.0f + expf(-logit));
    }
}

// ---------------- launch ----------------------------------------------------

extern "C" void kernel_launch(void* const* d_in, const int* in_sizes, int n_in,
                              void* d_out, int out_size) {
    const float* x_customer = (const float*)d_in[0];
    const float* x_product  = (const float*)d_in[1];
    const int*   edge_c2p   = (const int*)d_in[2];
    const int*   edge_p2c   = (const int*)d_in[3];
    const float* W1l_r1 = (const float*)d_in[4];
    const float* b1_r1  = (const float*)d_in[5];
    const float* W1r_r1 = (const float*)d_in[6];
    const float* W1l_r2 = (const float*)d_in[7];
    const float* b1_r2  = (const float*)d_in[8];
    const float* W1r_r2 = (const float*)d_in[9];
    const float* W2l_r1 = (const float*)d_in[10];
    const float* b2_r1  = (const float*)d_in[11];
    const float* W2r_r1 = (const float*)d_in[12];
    const float* Wlin   = (const float*)d_in[16];
    const float* blin   = (const float*)d_in[17];
    float* out = (float*)d_out;

    const int N = N_NODES;
    const int E = in_sizes[2] / 2;

    float *p_ycp, *p_ypc, *p_linc, *p_linp, *p_gc, *p_w2l, *p_w2r;
    int *p_cnt_p, *p_cnt_c, *p_off_p, *p_off_c, *p_cur_p, *p_cur_c, *p_adj_p, *p_adj_c;
    cudaGetSymbolAddress((void**)&p_ycp,  g_ycp);
    cudaGetSymbolAddress((void**)&p_ypc,  g_ypc);
    cudaGetSymbolAddress((void**)&p_linc, g_linc);
    cudaGetSymbolAddress((void**)&p_linp, g_linp);
    cudaGetSymbolAddress((void**)&p_gc,   g_gc);
    cudaGetSymbolAddress((void**)&p_w2l,  g_w2l_eff);
    cudaGetSymbolAddress((void**)&p_w2r,  g_w2r_eff);
    cudaGetSymbolAddress((void**)&p_cnt_p, g_cnt_p);
    cudaGetSymbolAddress((void**)&p_cnt_c, g_cnt_c);
    cudaGetSymbolAddress((void**)&p_off_p, g_off_p);
    cudaGetSymbolAddress((void**)&p_off_c, g_off_c);
    cudaGetSymbolAddress((void**)&p_cur_p, g_cur_p);
    cudaGetSymbolAddress((void**)&p_cur_c, g_cur_c);
    cudaGetSymbolAddress((void**)&p_adj_p, g_adj_p);
    cudaGetSymbolAddress((void**)&p_adj_c, g_adj_c);

    const int TB = 256;
    int gemmBlocks = (N + BM - 1) / BM;
    int edgeBlocks = (E + TB - 1) / TB;
    int nodeBlocks = (N + TB - 1) / TB;
    int warpBlocks = (N * 32 + TB - 1) / TB;   // warp per node

    // 0: zero degree counters
    k_zero_cnt<<<nodeBlocks, TB>>>();
    // 1: effective layer2 + head weights
    k_eff<<<1, 32>>>(W2l_r1, W2r_r1, b2_r1, Wlin, blin);
    // 2,3: dense preps
    k_prep<<<gemmBlocks, 256>>>(x_product,  W1l_r2, W1r_r1, b1_r1, p_ypc, p_linp, N);
    k_prep<<<gemmBlocks, 256>>>(x_customer, W1l_r1, W1r_r2, b1_r2, p_ycp, p_linc, N);
    // 4: degree counts (both relations)
    k_count<<<edgeBlocks, TB>>>(edge_c2p, edge_p2c, E);
    // 5,6: prefix scans -> CSR offsets + cursors
    k_scan<<<1, 1024>>>(p_cnt_p, p_off_p, p_cur_p, N);
    k_scan<<<1, 1024>>>(p_cnt_c, p_off_c, p_cur_c, N);
    // 7: adjacency fill (both relations)
    k_fill<<<edgeBlocks, TB>>>(edge_c2p, edge_p2c, E);
    // 8: customer gather -> g_c
    k_gather_c<<<warpBlocks, TB>>>(p_off_c, p_adj_c, p_ypc, p_linc, p_w2l, p_gc, N);
    // 9: product gather (layer1 + layer2 + head + sigmoid) -> out
    k_gather_p<<<warpBlocks, TB>>>(p_off_p, p_adj_p, p_ycp, p_linp, p_w2r, p_gc, out, N);
}

// round 11
// speedup vs baseline: 2.1536x; 2.1536x over previous
#include <cuda_runtime.h>
#include <cuda_bf16.h>
#include <math.h>

#define N_NODES 100000
#define D_IN    64
#define D_H     32
#define TOTAL_H (N_NODES * D_H)
#define BM      128
#define XS      (BM + 4)

// ---------------- scratch (device globals, 16B aligned) ---------------------
__device__ __align__(16) float g_aggp[TOTAL_H];
__device__ __align__(16) float g_aggc[TOTAL_H];
__device__ __align__(16) float g_ycp [TOTAL_H];
__device__ __align__(16) float g_ypc [TOTAL_H];
__device__ __align__(16) float g_linc[TOTAL_H];
__device__ __align__(16) float g_linp[TOTAL_H];
__device__ __align__(16) float g_cntp[N_NODES];
__device__ __align__(16) float g_cntc[N_NODES];
__device__ __align__(16) float g_gc  [N_NODES];
__device__ __align__(16) float g_aggs[N_NODES];
__device__ float g_w2l_eff[D_H];
__device__ float g_w2r_eff[D_H];
__device__ float g_bias_eff[1];

// ---------------- kernels ---------------------------------------------------

__global__ void k_zero_all() {
    int i = blockIdx.x * blockDim.x + threadIdx.x;
    int stride = gridDim.x * blockDim.x;
    float4 z = make_float4(0.f, 0.f, 0.f, 0.f);
    for (int k = i; k < TOTAL_H / 4; k += stride) {
        reinterpret_cast<float4*>(g_aggp)[k] = z;
        reinterpret_cast<float4*>(g_aggc)[k] = z;
    }
    for (int k = i; k < N_NODES / 4; k += stride) {
        reinterpret_cast<float4*>(g_cntp)[k] = z;
        reinterpret_cast<float4*>(g_cntc)[k] = z;
        reinterpret_cast<float4*>(g_aggs)[k] = z;
    }
}

__global__ void k_eff(const float* __restrict__ W2l, const float* __restrict__ W2r,
                      const float* __restrict__ b2, const float* __restrict__ Wlin,
                      const float* __restrict__ blin) {
    int i = threadIdx.x;  // 0..31
    float wl = 0.f, wr = 0.f;
    #pragma unroll
    for (int j = 0; j < D_H; ++j) {
        float wj = Wlin[j];
        wl += W2l[i * D_H + j] * wj;
        wr += W2r[i * D_H + j] * wj;
    }
    g_w2l_eff[i] = wl;
    g_w2r_eff[i] = wr;
    float bv = b2[i] * Wlin[i];
    #pragma unroll
    for (int o = 16; o; o >>= 1) bv += __shfl_xor_sync(0xffffffffu, bv, o);
    if (i == 0) g_bias_eff[0] = bv + blin[0];
}

// Register-tiled GEMM (proven): C[128 nodes][64 outs] = x @ [Wl | Wr], K=64.
__global__ void k_prep(const float* __restrict__ x,
                       const float* __restrict__ Wl, const float* __restrict__ Wr,
                       const float* __restrict__ b,
                       float* __restrict__ y, float* __restrict__ lin, int n) {
    __shared__ float sW[D_IN * 64];
    __shared__ float sX[D_IN * XS];
    __shared__ float sb2[D_H];
    int tid = threadIdx.x;

    for (int i = tid; i < D_IN * 8; i += 256) {
        int k = i >> 3, q = i & 7;
        reinterpret_cast<float4*>(sW)[k * 16 + q]     = reinterpret_cast<const float4*>(Wl)[i];
        reinterpret_cast<float4*>(sW)[k * 16 + 8 + q] = reinterpret_cast<const float4*>(Wr)[i];
    }
    if (tid < D_H) sb2[tid] = b[tid];

    int base = blockIdx.x * BM;
    for (int i = tid; i < BM * 16; i += 256) {
        int node = i >> 4;
        int q    = i & 15;
        int gn = base + node;
        float4 v = (gn < n) ? reinterpret_cast<const float4*>(x + (size_t)gn * D_IN)[q]
                            : make_float4(0.f, 0.f, 0.f, 0.f);
        int k4 = q * 4;
        sX[(k4 + 0) * XS + node] = v.x;
        sX[(k4 + 1) * XS + node] = v.y;
        sX[(k4 + 2) * XS + node] = v.z;
        sX[(k4 + 3) * XS + node] = v.w;
    }
    __syncthreads();

    int tn = tid & 15;
    int tm = tid >> 4;
    int n0 = tn * 4, m0 = tm * 8;

    float acc[8][4];
    #pragma unroll
    for (int i = 0; i < 8; ++i)
        #pragma unroll
        for (int j = 0; j < 4; ++j) acc[i][j] = 0.f;

    #pragma unroll 4
    for (int k = 0; k < D_IN; ++k) {
        float4 w  = *reinterpret_cast<const float4*>(&sW[k * 64 + n0]);
        float4 xa = *reinterpret_cast<const float4*>(&sX[k * XS + m0]);
        float4 xb = *reinterpret_cast<const float4*>(&sX[k * XS + m0 + 4]);
        float xm[8] = {xa.x, xa.y, xa.z, xa.w, xb.x, xb.y, xb.z, xb.w};
        #pragma unroll
        for (int i = 0; i < 8; ++i) {
            acc[i][0] += xm[i] * w.x;
            acc[i][1] += xm[i] * w.y;
            acc[i][2] += xm[i] * w.z;
            acc[i][3] += xm[i] * w.w;
        }
    }

    bool isLin = (tn >= 8);
    int col = isLin ? (n0 - 32) : n0;
    float4 bw = isLin ? *reinterpret_cast<const float4*>(&sb2[col])
                      : make_float4(0.f, 0.f, 0.f, 0.f);
    float* dst = isLin ? lin : y;
    #pragma unroll
    for (int i = 0; i < 8; ++i) {
        int gn = base + m0 + i;
        if (gn < n) {
            float4 v = make_float4(acc[i][0] + bw.x, acc[i][1] + bw.y,
                                   acc[i][2] + bw.z, acc[i][3] + bw.w);
            *reinterpret_cast<float4*>(dst + (size_t)gn * D_H + col) = v;
        }
    }
}

// BOTH relations' layer-1 scatters in one launch (independent work, 2E edges).
// 8 threads/edge; 8 lanes cover one 128B dst row (coalesced RED.128 wavefronts).
__global__ void k_scatter_both(const int* __restrict__ e_p2c, const int* __restrict__ e_c2p,
                               int E) {
    long long t = (long long)blockIdx.x * blockDim.x + threadIdx.x;
    int e    = (int)(t >> 3);
    int lane = (int)(t & 7);
    if (e >= 2 * E) return;
    const int* edge;
    const float* feat;
    float* agg;
    float* cnt;
    if (e < E) {
        edge = e_p2c; feat = g_ypc; agg = g_aggc; cnt = g_cntc;
    } else {
        e -= E;
        edge = e_c2p; feat = g_ycp; agg = g_aggp; cnt = g_cntp;
    }
    int s = __ldg(&edge[e]);
    int d = __ldg(&edge[E + e]);
    float4 v = *reinterpret_cast<const float4*>(feat + (size_t)s * D_H + lane * 4);
    atomicAdd(reinterpret_cast<float4*>(agg + (size_t)d * D_H + lane * 4), v);
    if (lane == 0) atomicAdd(cnt + d, 1.0f);
}

// Layer-2 scalar scatter: aggs[d] += g_c[s] over c2p edges. 1 thread/edge.
__global__ void k_scatter_scalar(const int* __restrict__ edge, int E) {
    int e = blockIdx.x * blockDim.x + threadIdx.x;
    if (e >= E) return;
    int s = __ldg(&edge[e]);
    int d = __ldg(&edge[E + e]);
    atomicAdd(&g_aggs[d], __ldg(&g_gc[s]));
}

// Customer post: h = relu(agg/max(cnt,1) + lin); g = dot(h, weff). Warp/node.
__global__ void k_post_c(const float* __restrict__ agg, const float* __restrict__ cnt,
                         const float* __restrict__ lin, const float* __restrict__ weff,
                         float* __restrict__ g, int n) {
    int j = threadIdx.x & 31;
    int warpId = (blockIdx.x * blockDim.x + threadIdx.x) >> 5;
    int nWarps = (gridDim.x * blockDim.x) >> 5;
    float wj = weff[j];
    for (int node = warpId; node < n; node += nWarps) {
        float inv = 1.0f / fmaxf(cnt[node], 1.0f);
        float h = fmaxf(agg[(size_t)node * D_H + j] * inv + lin[(size_t)node * D_H + j], 0.f);
        float v = h * wj;
        #pragma unroll
        for (int o = 16; o; o >>= 1) v += __shfl_xor_sync(0xffffffffu, v, o);
        if (j == 0) g[node] = v;
    }
}

// Product post: + layer2 mean + sigmoid -> out.
__global__ void k_post_p(const float* __restrict__ agg, const float* __restrict__ cnt,
                         const float* __restrict__ lin, const float* __restrict__ weff,
                         const float* __restrict__ aggs, float* __restrict__ out, int n) {
    int j = threadIdx.x & 31;
    int warpId = (blockIdx.x * blockDim.x + threadIdx.x) >> 5;
    int nWarps = (gridDim.x * blockDim.x) >> 5;
    float wj = weff[j];
    float beff = g_bias_eff[0];
    for (int node = warpId; node < n; node += nWarps) {
        float inv = 1.0f / fmaxf(cnt[node], 1.0f);
        float h = fmaxf(agg[(size_t)node * D_H + j] * inv + lin[(size_t)node * D_H + j], 0.f);
        float v = h * wj;
        #pragma unroll
        for (int o = 16; o; o >>= 1) v += __shfl_xor_sync(0xffffffffu, v, o);
        if (j == 0) {
            float logit = aggs[node] * inv + v + beff;
            out[node] = 1.0f / (1.0f + expf(-logit));
        }
    }
}

// ---------------- launch ----------------------------------------------------

extern "C" void kernel_launch(void* const* d_in, const int* in_sizes, int n_in,
                              void* d_out, int out_size) {
    const float* x_customer = (const float*)d_in[0];
    const float* x_product  = (const float*)d_in[1];
    const int*   edge_c2p   = (const int*)d_in[2];
    const int*   edge_p2c   = (const int*)d_in[3];
    const float* W1l_r1 = (const float*)d_in[4];
    const float* b1_r1  = (const float*)d_in[5];
    const float* W1r_r1 = (const float*)d_in[6];
    const float* W1l_r2 = (const float*)d_in[7];
    const float* b1_r2  = (const float*)d_in[8];
    const float* W1r_r2 = (const float*)d_in[9];
    const float* W2l_r1 = (const float*)d_in[10];
    const float* b2_r1  = (const float*)d_in[11];
    const float* W2r_r1 = (const float*)d_in[12];
    const float* Wlin   = (const float*)d_in[16];
    const float* blin   = (const float*)d_in[17];
    float* out = (float*)d_out;

    const int N = N_NODES;
    const int E = in_sizes[2] / 2;

    float *p_aggp, *p_aggc, *p_ycp, *p_ypc, *p_linc, *p_linp;
    float *p_cntp, *p_cntc, *p_gc, *p_aggs, *p_w2l, *p_w2r;
    cudaGetSymbolAddress((void**)&p_aggp, g_aggp);
    cudaGetSymbolAddress((void**)&p_aggc, g_aggc);
    cudaGetSymbolAddress((void**)&p_ycp,  g_ycp);
    cudaGetSymbolAddress((void**)&p_ypc,  g_ypc);
    cudaGetSymbolAddress((void**)&p_linc, g_linc);
    cudaGetSymbolAddress((void**)&p_linp, g_linp);
    cudaGetSymbolAddress((void**)&p_cntp, g_cntp);
    cudaGetSymbolAddress((void**)&p_cntc, g_cntc);
    cudaGetSymbolAddress((void**)&p_gc,   g_gc);
    cudaGetSymbolAddress((void**)&p_aggs, g_aggs);
    cudaGetSymbolAddress((void**)&p_w2l,  g_w2l_eff);
    cudaGetSymbolAddress((void**)&p_w2r,  g_w2r_eff);

    const int TB = 256;
    const int GS_BLOCKS = 1480;
    int gemmBlocks = (N + BM - 1) / BM;

    long long bothThreads = (long long)(2 * E) * 8;
    int bothBlocks = (int)((bothThreads + TB - 1) / TB);
    int edgeBlocks = (E + TB - 1) / TB;

    // 0: zero all accumulators
    k_zero_all<<<1024, TB>>>();
    // 1: effective layer2 + head weights
    k_eff<<<1, 32>>>(W2l_r1, W2r_r1, b2_r1, Wlin, blin);
    // 2: product prep  (y_pc = x_p@W1l_r2, lin_p = x_p@W1r_r1 + b1_r1)
    k_prep<<<gemmBlocks, 256>>>(x_product, W1l_r2, W1r_r1, b1_r1, p_ypc, p_linp, N);
    // 3: customer prep (y_cp = x_c@W1l_r1, lin_c = x_c@W1r_r2 + b1_r2)
    k_prep<<<gemmBlocks, 256>>>(x_customer, W1l_r1, W1r_r2, b1_r2, p_ycp, p_linc, N);
    // 4: BOTH layer-1 scatters in one launch  <-- profiled launch
    k_scatter_both<<<bothBlocks, TB>>>(edge_p2c, edge_c2p, E);
    // 5: customer post -> g_c
    k_post_c<<<GS_BLOCKS, TB>>>(p_aggc, p_cntc, p_linc, p_w2l, p_gc, N);
    // 6: layer-2 scalar scatter over c2p
    k_scatter_scalar<<<edgeBlocks, TB>>>(edge_c2p, E);
    // 7: product post + head + sigmoid
    k_post_p<<<GS_BLOCKS, TB>>>(p_aggp, p_cntp, p_linp, p_w2r, p_aggs, out, N);
}